// round 2
// baseline (speedup 1.0000x reference)
#include <cuda_runtime.h>
#include <math.h>
#include <float.h>

#define BATCH 2
#define NP    32768
#define NLEV  4
#define TPB   32          // one warp per block
#define PPT   2           // points per thread
#define PTS   (TPB*PPT)   // 64 points per block
#define TPAIRS 512        // voxel pairs per smem tile (1024 voxels, 16KB)
#define PB    64          // stats partial blocks per batch
#define MARGIN 0.0625f

typedef unsigned long long ull;

// ---------------- scratch (device globals; no allocations allowed) ----------
__device__ int   g_idx [NLEV * BATCH * NP * 3];
__device__ float g_w   [NLEV * BATCH * NP * 3];
__device__ float g_psum[BATCH * PB * 256];
__device__ float g_psqs[BATCH * PB * 256];
__device__ float g_mu  [BATCH * 256];
__device__ float g_rstd[BATCH * 256];

// ---------------- packed f32x2 helpers ---------------------------------------
__device__ __forceinline__ ull pack2(float v) {
    ull r; asm("mov.b64 %0, {%1, %1};" : "=l"(r) : "f"(v)); return r;
}
__device__ __forceinline__ ull ffma2(ull a, ull b, ull c) {
    ull d; asm("fma.rn.f32x2 %0, %1, %2, %3;" : "=l"(d) : "l"(a), "l"(b), "l"(c));
    return d;
}
__device__ __forceinline__ float f2lo(ull v) { return __uint_as_float((unsigned)v); }
__device__ __forceinline__ float f2hi(ull v) { return __uint_as_float((unsigned)(v >> 32)); }

// ---------------- KNN: 1 warp/block, all 4 levels per block (perfect balance)
// Screen s = 0.5|v|^2 - p.v in packed f32x2 (2 voxels x 2 points). Exact fp32
// (p-v)^2 recompute on the rare pass path decides all insertions, so the
// selected top-3 set matches the reference brute force (margin covers the
// fp32 error of the fast form).
__global__ __launch_bounds__(TPB) void knn_kernel(
    const float* __restrict__ pt,
    const float* __restrict__ vc0, const float* __restrict__ vc1,
    const float* __restrict__ vc2, const float* __restrict__ vc3,
    int nv0, int nv1, int nv2, int nv3)
{
    __shared__ float4 svA[TPAIRS];   // {x0,x1,y0,y1}
    __shared__ float4 svB[TPAIRS];   // {z0,z1,h0,h1}

    const int b     = blockIdx.y;
    const int pbase = blockIdx.x * PTS;
    const int lane  = threadIdx.x;

    float px[PPT], py[PPT], pz[PPT], pp[PPT];
    ull   nx[PPT], ny[PPT], nz[PPT];
    #pragma unroll
    for (int r = 0; r < PPT; r++) {
        int p = pbase + lane + r * TPB;
        const float* q = pt + ((size_t)b * NP + p) * 3;
        px[r] = q[0]; py[r] = q[1]; pz[r] = q[2];
        pp[r] = fmaf(px[r], px[r], fmaf(py[r], py[r], pz[r] * pz[r]));
        nx[r] = pack2(-px[r]); ny[r] = pack2(-py[r]); nz[r] = pack2(-pz[r]);
    }

    const float* vcs[4] = { vc0, vc1, vc2, vc3 };
    const int    nvs[4] = { nv0, nv1, nv2, nv3 };

    for (int lv = 0; lv < NLEV; lv++) {
        const int Nv = nvs[lv];
        const float* vcb = vcs[lv] + (size_t)b * Nv * 3;
        const int npairs = Nv >> 1;

        float b0[PPT], b1[PPT], b2[PPT], sthr[PPT];
        int   i0[PPT], i1[PPT], i2[PPT];
        #pragma unroll
        for (int r = 0; r < PPT; r++) {
            b0[r] = b1[r] = b2[r] = FLT_MAX;
            i0[r] = i1[r] = i2[r] = 0;
            sthr[r] = 0.5f * (FLT_MAX - pp[r]);  // effectively +inf threshold
        }

        for (int tb = 0; tb < npairs; tb += TPAIRS) {
            const int tn = min(TPAIRS, npairs - tb);
            __syncwarp();
            for (int j = lane; j < tn; j += TPB) {
                const float* v = vcb + (size_t)(tb + j) * 6;
                float x0 = v[0], y0 = v[1], z0 = v[2];
                float x1 = v[3], y1 = v[4], z1 = v[5];
                float h0 = 0.5f * fmaf(x0, x0, fmaf(y0, y0, z0 * z0));
                float h1 = 0.5f * fmaf(x1, x1, fmaf(y1, y1, z1 * z1));
                svA[j] = make_float4(x0, x1, y0, y1);
                svB[j] = make_float4(z0, z1, h0, h1);
            }
            __syncwarp();

            const ulonglong2* A64 = (const ulonglong2*)svA;
            const ulonglong2* B64 = (const ulonglong2*)svB;

            #pragma unroll 4
            for (int j = 0; j < tn; j++) {
                ulonglong2 A  = A64[j];   // .x={x0,x1} .y={y0,y1}
                ulonglong2 Bv = B64[j];   // .x={z0,z1} .y={h0,h1}
                bool hit = false;
                #pragma unroll
                for (int r = 0; r < PPT; r++) {
                    ull s = ffma2(nx[r], A.x, Bv.y);
                    s = ffma2(ny[r], A.y, s);
                    s = ffma2(nz[r], Bv.x, s);
                    hit |= (fminf(f2lo(s), f2hi(s)) < sthr[r]);
                }
                if (hit) {                 // rare: exact fp32 path, regs only
                    float x0 = f2lo(A.x),  x1 = f2hi(A.x);
                    float y0 = f2lo(A.y),  y1 = f2hi(A.y);
                    float z0 = f2lo(Bv.x), z1 = f2hi(Bv.x);
                    const int vbase = (tb + j) * 2;
                    #pragma unroll
                    for (int r = 0; r < PPT; r++) {
                        #pragma unroll
                        for (int t = 0; t < 2; t++) {
                            float vx = t ? x1 : x0;
                            float vy = t ? y1 : y0;
                            float vz = t ? z1 : z0;
                            float dx = px[r] - vx, dy = py[r] - vy, dz = pz[r] - vz;
                            float d2 = fmaf(dx, dx, fmaf(dy, dy, dz * dz));
                            if (d2 < b2[r]) {
                                int idx = vbase + t;
                                if (d2 < b1[r]) {
                                    b2[r] = b1[r]; i2[r] = i1[r];
                                    if (d2 < b0[r]) { b1[r] = b0[r]; i1[r] = i0[r];
                                                      b0[r] = d2;    i0[r] = idx; }
                                    else            { b1[r] = d2;    i1[r] = idx; }
                                } else { b2[r] = d2; i2[r] = idx; }
                            }
                        }
                        sthr[r] = 0.5f * (b2[r] + MARGIN - pp[r]);
                    }
                }
            }
        }

        // inverse-distance weights (matches reference 1/(sqrt(d2)+1e-8))
        #pragma unroll
        for (int r = 0; r < PPT; r++) {
            float w0 = 1.0f / (sqrtf(b0[r]) + 1e-8f);
            float w1 = 1.0f / (sqrtf(b1[r]) + 1e-8f);
            float w2 = 1.0f / (sqrtf(b2[r]) + 1e-8f);
            float inv = 1.0f / (w0 + w1 + w2);
            int p = pbase + lane + r * TPB;
            size_t o = ((size_t)lv * BATCH * NP + (size_t)b * NP + p) * 3;
            g_idx[o] = i0[r]; g_idx[o + 1] = i1[r]; g_idx[o + 2] = i2[r];
            g_w[o] = w0 * inv; g_w[o + 1] = w1 * inv; g_w[o + 2] = w2 * inv;
        }
    }
}

// ---------------- interpolation: warp per point, coalesced channel gather ----
__global__ __launch_bounds__(256) void interp_kernel(
    const float* __restrict__ vf, float* __restrict__ out,
    int Nv, int C, int lv)
{
    const int lane = threadIdx.x & 31;
    const int wid  = threadIdx.x >> 5;
    const int p    = blockIdx.x * (blockDim.x >> 5) + wid;
    const int b    = blockIdx.y;

    size_t o = ((size_t)lv * BATCH * NP + (size_t)b * NP + p) * 3;
    int   i0 = g_idx[o], i1 = g_idx[o + 1], i2 = g_idx[o + 2];
    float w0 = g_w[o],   w1 = g_w[o + 1],   w2 = g_w[o + 2];

    const float* f0 = vf + ((size_t)b * Nv + i0) * C;
    const float* f1 = vf + ((size_t)b * Nv + i1) * C;
    const float* f2 = vf + ((size_t)b * Nv + i2) * C;
    float* op = out + ((size_t)b * NP + p) * C;

    for (int c = lane; c < C; c += 32)
        op[c] = fmaf(w2, f2[c], fmaf(w1, f1[c], w0 * f0[c]));
}

// ---------------- BN stats: coalesced per-channel partial sums ---------------
__global__ void stats_partial_kernel(const float* __restrict__ x, int C)
{
    const int c   = threadIdx.x;      // blockDim.x == C
    const int b   = blockIdx.y;
    const int blk = blockIdx.x;       // PB blocks per batch
    const int pn  = NP / PB;

    const float* xb = x + ((size_t)b * NP + (size_t)blk * pn) * C + c;
    float s = 0.f, q = 0.f;
    for (int p = 0; p < pn; p++) {
        float v = xb[(size_t)p * C];
        s += v;
        q = fmaf(v, v, q);
    }
    g_psum[((size_t)b * PB + blk) * C + c] = s;
    g_psqs[((size_t)b * PB + blk) * C + c] = q;
}

__global__ void stats_final_kernel(int C)
{
    int i = blockIdx.x * blockDim.x + threadIdx.x;
    if (i >= BATCH * C) return;
    int b = i / C, c = i % C;
    float s = 0.f, q = 0.f;
    for (int k = 0; k < PB; k++) {
        s += g_psum[((size_t)b * PB + k) * C + c];
        q += g_psqs[((size_t)b * PB + k) * C + c];
    }
    float m   = s * (1.0f / NP);
    float var = q * (1.0f / NP) - m * m;      // biased var, matches jnp.var
    g_mu[b * C + c]   = m;
    g_rstd[b * C + c] = rsqrtf(var + 1e-5f);
}

// ---------------- normalize in place -----------------------------------------
__global__ __launch_bounds__(256) void normalize_kernel(
    float* __restrict__ x,
    const float* __restrict__ gamma, const float* __restrict__ beta, int C)
{
    int i = blockIdx.x * blockDim.x + threadIdx.x;   // within one batch: NP*C
    int b = blockIdx.y;
    int c = i % C;
    size_t idx = (size_t)b * NP * C + i;
    float m = g_mu[b * C + c], r = g_rstd[b * C + c];
    x[idx] = fmaf(gamma[c] * r, x[idx] - m, beta[c]);
}

// ---------------- launch ------------------------------------------------------
extern "C" void kernel_launch(void* const* d_in, const int* in_sizes, int n_in,
                              void* d_out, int out_size)
{
    const float* pt  = (const float*)d_in[0];
    float*       out = (float*)d_out;

    int nv[NLEV], cs[NLEV];
    for (int L = 0; L < NLEV; L++) {
        nv[L] = in_sizes[1 + 4 * L] / (BATCH * 3);
        cs[L] = in_sizes[2 + 4 * L] / (BATCH * nv[L]);
    }

    // one warp-block per 64-point chunk; each block scans all 4 levels
    knn_kernel<<<dim3(NP / PTS, BATCH), TPB>>>(
        pt,
        (const float*)d_in[1], (const float*)d_in[5],
        (const float*)d_in[9], (const float*)d_in[13],
        nv[0], nv[1], nv[2], nv[3]);

    size_t off = 0;
    for (int L = 0; L < NLEV; L++) {
        const float* vf    = (const float*)d_in[2 + 4 * L];
        const float* gamma = (const float*)d_in[3 + 4 * L];
        const float* beta  = (const float*)d_in[4 + 4 * L];
        const int C = cs[L];
        float* o = out + off;

        interp_kernel<<<dim3(NP / 8, BATCH), 256>>>(vf, o, nv[L], C, L);
        stats_partial_kernel<<<dim3(PB, BATCH), C>>>(o, C);
        stats_final_kernel<<<1, 512>>>(C);
        normalize_kernel<<<dim3(NP * C / 256, BATCH), 256>>>(o, gamma, beta, C);

        off += (size_t)BATCH * NP * C;
    }
    (void)n_in; (void)out_size;
}

// round 4
// speedup vs baseline: 3.6445x; 3.6445x over previous
#include <cuda_runtime.h>
#include <math.h>
#include <float.h>

#define BATCH 2
#define NP    32768
#define NLEV  4
#define NSLOT 8            // (level, batch) slots
#define PB    256          // stats partial chunks per batch
#define MAXC  256

// ---------------- static device scratch (no allocations allowed) ------------
__device__ unsigned g_bb  [NSLOT * 6];      // encoded bbox: min x,y,z / max x,y,z
__device__ int      g_cnt [90000];
__device__ int      g_off [90000];          // +1 sentinel per slot
__device__ int      g_fill[90000];
__device__ float4   g_svox[131072];         // binned voxels {x,y,z,idx-bits}
__device__ int      g_idx [NLEV * BATCH * NP * 3];
__device__ float    g_w   [NLEV * BATCH * NP * 3];
__device__ float    g_psum[BATCH * PB * MAXC];
__device__ float    g_psqs[BATCH * PB * MAXC];
__device__ float    g_mu  [BATCH * MAXC];
__device__ float    g_rstd[BATCH * MAXC];

struct GridParams {
    const float* vc[NSLOT];
    int nv[NSLOT];
    int gs[NSLOT];
    int cellbase[NSLOT];
    int offbase[NSLOT];
    int svbase[NSLOT];
};

// order-preserving float <-> uint for atomicMin/Max
__device__ __forceinline__ unsigned fenc(float f) {
    unsigned u = __float_as_uint(f);
    return (u & 0x80000000u) ? ~u : (u | 0x80000000u);
}
__device__ __forceinline__ float fdec(unsigned u) {
    unsigned v = (u & 0x80000000u) ? (u & 0x7FFFFFFFu) : ~u;
    return __uint_as_float(v);
}
__device__ __forceinline__ int clampi(int v, int lo, int hi) {
    return v < lo ? lo : (v > hi ? hi : v);
}

// ---------------- init ------------------------------------------------------
__global__ void init_kernel(int totcells) {
    int i = blockIdx.x * blockDim.x + threadIdx.x;
    if (i < totcells) { g_cnt[i] = 0; g_fill[i] = 0; }
    if (i < NSLOT * 6) g_bb[i] = (i % 6 < 3) ? 0xFFFFFFFFu : 0u;
}

// ---------------- per-slot bbox ---------------------------------------------
__global__ void bbox_kernel(GridParams gp) {
    int s = blockIdx.y;
    int nv = gp.nv[s];
    int i = blockIdx.x * 256 + threadIdx.x;
    float x = FLT_MAX, y = FLT_MAX, z = FLT_MAX;
    float X = -FLT_MAX, Y = -FLT_MAX, Z = -FLT_MAX;
    if (i < nv) {
        const float* v = gp.vc[s] + (size_t)i * 3;
        x = X = v[0]; y = Y = v[1]; z = Z = v[2];
    }
    #pragma unroll
    for (int d = 16; d; d >>= 1) {
        x = fminf(x, __shfl_xor_sync(0xFFFFFFFFu, x, d));
        y = fminf(y, __shfl_xor_sync(0xFFFFFFFFu, y, d));
        z = fminf(z, __shfl_xor_sync(0xFFFFFFFFu, z, d));
        X = fmaxf(X, __shfl_xor_sync(0xFFFFFFFFu, X, d));
        Y = fmaxf(Y, __shfl_xor_sync(0xFFFFFFFFu, Y, d));
        Z = fmaxf(Z, __shfl_xor_sync(0xFFFFFFFFu, Z, d));
    }
    if ((threadIdx.x & 31) == 0) {
        atomicMin(&g_bb[s * 6 + 0], fenc(x));
        atomicMin(&g_bb[s * 6 + 1], fenc(y));
        atomicMin(&g_bb[s * 6 + 2], fenc(z));
        atomicMax(&g_bb[s * 6 + 3], fenc(X));
        atomicMax(&g_bb[s * 6 + 4], fenc(Y));
        atomicMax(&g_bb[s * 6 + 5], fenc(Z));
    }
}

// identical cell computation used by count / scatter / query
__device__ __forceinline__ void load_grid(int s, int gs,
    float& bx0, float& by0, float& bz0, float& sx, float& sy, float& sz) {
    bx0 = fdec(g_bb[s * 6 + 0]); by0 = fdec(g_bb[s * 6 + 1]); bz0 = fdec(g_bb[s * 6 + 2]);
    float bx1 = fdec(g_bb[s * 6 + 3]), by1 = fdec(g_bb[s * 6 + 4]), bz1 = fdec(g_bb[s * 6 + 5]);
    sx = gs / fmaxf(bx1 - bx0, 1e-9f);
    sy = gs / fmaxf(by1 - by0, 1e-9f);
    sz = gs / fmaxf(bz1 - bz0, 1e-9f);
}

// ---------------- count -----------------------------------------------------
__global__ void count_kernel(GridParams gp) {
    int s = blockIdx.y;
    int nv = gp.nv[s];
    int i = blockIdx.x * 256 + threadIdx.x;
    if (i >= nv) return;
    int gs = gp.gs[s];
    float bx0, by0, bz0, sx, sy, sz;
    load_grid(s, gs, bx0, by0, bz0, sx, sy, sz);
    const float* v = gp.vc[s] + (size_t)i * 3;
    int cx = clampi((int)((v[0] - bx0) * sx), 0, gs - 1);
    int cy = clampi((int)((v[1] - by0) * sy), 0, gs - 1);
    int cz = clampi((int)((v[2] - bz0) * sz), 0, gs - 1);
    atomicAdd(&g_cnt[gp.cellbase[s] + (cz * gs + cy) * gs + cx], 1);
}

// ---------------- exclusive scan, one block per slot -------------------------
__global__ void scan_kernel(GridParams gp) {
    int s = blockIdx.x;
    int gs = gp.gs[s];
    int n = gs * gs * gs;
    int base = gp.cellbase[s], obase = gp.offbase[s];
    int t = threadIdx.x, lane = t & 31, wid = t >> 5;
    __shared__ int wsum[32];
    int running = 0;
    for (int c0 = 0; c0 < n; c0 += 1024) {
        int v = (c0 + t < n) ? g_cnt[base + c0 + t] : 0;
        int sv = v;
        #pragma unroll
        for (int d = 1; d < 32; d <<= 1) {
            int o = __shfl_up_sync(0xFFFFFFFFu, sv, d);
            if (lane >= d) sv += o;
        }
        if (lane == 31) wsum[wid] = sv;
        __syncthreads();
        if (wid == 0) {
            int ws = wsum[lane];
            #pragma unroll
            for (int d = 1; d < 32; d <<= 1) {
                int o = __shfl_up_sync(0xFFFFFFFFu, ws, d);
                if (lane >= d) ws += o;
            }
            wsum[lane] = ws;
        }
        __syncthreads();
        int incl = sv + (wid ? wsum[wid - 1] : 0);
        if (c0 + t < n) g_off[obase + c0 + t] = running + incl - v;
        int tot = wsum[31];
        __syncthreads();
        running += tot;
    }
    if (t == 0) g_off[obase + n] = running;
}

// ---------------- scatter ----------------------------------------------------
__global__ void scatter_kernel(GridParams gp) {
    int s = blockIdx.y;
    int nv = gp.nv[s];
    int i = blockIdx.x * 256 + threadIdx.x;
    if (i >= nv) return;
    int gs = gp.gs[s];
    float bx0, by0, bz0, sx, sy, sz;
    load_grid(s, gs, bx0, by0, bz0, sx, sy, sz);
    const float* v = gp.vc[s] + (size_t)i * 3;
    float x = v[0], y = v[1], z = v[2];
    int cx = clampi((int)((x - bx0) * sx), 0, gs - 1);
    int cy = clampi((int)((y - by0) * sy), 0, gs - 1);
    int cz = clampi((int)((z - bz0) * sz), 0, gs - 1);
    int cell = (cz * gs + cy) * gs + cx;
    int pos = g_off[gp.offbase[s] + cell] + atomicAdd(&g_fill[gp.cellbase[s] + cell], 1);
    g_svox[gp.svbase[s] + pos] = make_float4(x, y, z, __int_as_float(i));
}

// ---------------- query: exact 3-NN via expanding shells ---------------------
__device__ __forceinline__ void scan_cell(int cell, int ob, int sb,
    float qx, float qy, float qz,
    float& b0, float& b1, float& b2, int& i0, int& i1, int& i2)
{
    int st = __ldg(&g_off[ob + cell]), en = __ldg(&g_off[ob + cell + 1]);
    for (int j = st; j < en; j++) {
        float4 v = __ldg(&g_svox[sb + j]);
        float dx = qx - v.x, dy = qy - v.y, dz = qz - v.z;
        float d2 = fmaf(dx, dx, fmaf(dy, dy, dz * dz));
        if (d2 < b2) {
            int idx = __float_as_int(v.w);
            if (d2 < b1) {
                b2 = b1; i2 = i1;
                if (d2 < b0) { b1 = b0; i1 = i0; b0 = d2; i0 = idx; }
                else         { b1 = d2; i1 = idx; }
            } else { b2 = d2; i2 = idx; }
        }
    }
}

__global__ __launch_bounds__(256) void query_kernel(
    const float* __restrict__ pt, GridParams gp)
{
    int gid = blockIdx.x * 256 + threadIdx.x;   // over NLEV*BATCH*NP
    int p  = gid & (NP - 1);
    int bl = gid >> 15;                         // 0..7
    int b  = bl & 1;
    int L  = bl >> 1;
    int s  = L * 2 + b;

    const float* q3 = pt + ((size_t)b * NP + p) * 3;
    float qx = q3[0], qy = q3[1], qz = q3[2];

    int gs = gp.gs[s];
    float bx0, by0, bz0, sx, sy, sz;
    load_grid(s, gs, bx0, by0, bz0, sx, sy, sz);
    float csx = 1.0f / sx, csy = 1.0f / sy, csz = 1.0f / sz;

    int cx = clampi((int)((qx - bx0) * sx), 0, gs - 1);
    int cy = clampi((int)((qy - by0) * sy), 0, gs - 1);
    int cz = clampi((int)((qz - bz0) * sz), 0, gs - 1);

    const int ob = gp.offbase[s];
    const int sb = gp.svbase[s];

    float b0 = FLT_MAX, b1 = FLT_MAX, b2 = FLT_MAX;
    int i0 = 0, i1 = 0, i2 = 0;

    for (int R = 0; R <= 2 * gs; R++) {
        int zlo = max(cz - R, 0), zhi = min(cz + R, gs - 1);
        for (int z = zlo; z <= zhi; z++) {
            bool zedge = (z == cz - R) || (z == cz + R);
            int ylo = max(cy - R, 0), yhi = min(cy + R, gs - 1);
            for (int y = ylo; y <= yhi; y++) {
                bool yedge = (y == cy - R) || (y == cy + R);
                int rowbase = (z * gs + y) * gs;
                if (zedge || yedge) {
                    int xlo = max(cx - R, 0), xhi = min(cx + R, gs - 1);
                    for (int x = xlo; x <= xhi; x++)
                        scan_cell(rowbase + x, ob, sb, qx, qy, qz, b0, b1, b2, i0, i1, i2);
                } else {
                    int xm = cx - R;
                    if (xm >= 0) scan_cell(rowbase + xm, ob, sb, qx, qy, qz, b0, b1, b2, i0, i1, i2);
                    int xp = cx + R;
                    if (xp < gs) scan_cell(rowbase + xp, ob, sb, qx, qy, qz, b0, b1, b2, i0, i1, i2);
                }
            }
        }
        // clearance of scanned box (per-dim; grid-edge faces are fully covered)
        float cl = FLT_MAX;
        if (cx - R > 0)      cl = fminf(cl, qx - (bx0 + (cx - R) * csx));
        if (cx + R < gs - 1) cl = fminf(cl, (bx0 + (cx + R + 1) * csx) - qx);
        if (cy - R > 0)      cl = fminf(cl, qy - (by0 + (cy - R) * csy));
        if (cy + R < gs - 1) cl = fminf(cl, (by0 + (cy + R + 1) * csy) - qy);
        if (cz - R > 0)      cl = fminf(cl, qz - (bz0 + (cz - R) * csz));
        if (cz + R < gs - 1) cl = fminf(cl, (bz0 + (cz + R + 1) * csz) - qz);
        if (cl == FLT_MAX) break;                 // whole grid scanned
        cl -= 1e-3f;                              // fp safety slack
        if (cl > 0.0f && b2 <= cl * cl) break;
    }

    float w0 = 1.0f / (sqrtf(b0) + 1e-8f);
    float w1 = 1.0f / (sqrtf(b1) + 1e-8f);
    float w2 = 1.0f / (sqrtf(b2) + 1e-8f);
    float inv = 1.0f / (w0 + w1 + w2);

    size_t o = ((size_t)L * BATCH * NP + (size_t)b * NP + p) * 3;
    g_idx[o] = i0; g_idx[o + 1] = i1; g_idx[o + 2] = i2;
    g_w[o] = w0 * inv; g_w[o + 1] = w1 * inv; g_w[o + 2] = w2 * inv;
}

// ---------------- epilogue pass A: interp-on-the-fly -> BN partial stats -----
__global__ void statsA_kernel(const float* __restrict__ vf, int Nv, int C, int lv)
{
    const int c   = threadIdx.x;            // blockDim.x == C
    const int b   = blockIdx.y;
    const int blk = blockIdx.x;             // PB chunks
    const int pn  = NP / PB;                // 128

    const float* base = vf + (size_t)b * Nv * C;
    float s = 0.f, q = 0.f;
    int p0 = blk * pn;
    for (int k = 0; k < pn; k++) {
        size_t o = ((size_t)lv * BATCH * NP + (size_t)b * NP + (p0 + k)) * 3;
        int   i0 = g_idx[o], i1 = g_idx[o + 1], i2 = g_idx[o + 2];
        float w0 = g_w[o],   w1 = g_w[o + 1],   w2 = g_w[o + 2];
        float v = fmaf(w2, __ldg(&base[(size_t)i2 * C + c]),
                  fmaf(w1, __ldg(&base[(size_t)i1 * C + c]),
                       w0 * __ldg(&base[(size_t)i0 * C + c])));
        s += v;
        q = fmaf(v, v, q);
    }
    g_psum[((size_t)b * PB + blk) * C + c] = s;
    g_psqs[((size_t)b * PB + blk) * C + c] = q;
}

__global__ void stats_final_kernel(int C)
{
    int i = blockIdx.x * blockDim.x + threadIdx.x;
    if (i >= BATCH * C) return;
    int b = i / C, c = i % C;
    float s = 0.f, q = 0.f;
    for (int k = 0; k < PB; k++) {
        s += g_psum[((size_t)b * PB + k) * C + c];
        q += g_psqs[((size_t)b * PB + k) * C + c];
    }
    float m   = s * (1.0f / NP);
    float var = q * (1.0f / NP) - m * m;      // biased var, matches jnp.var
    g_mu[b * C + c]   = m;
    g_rstd[b * C + c] = rsqrtf(var + 1e-5f);
}

// ---------------- epilogue pass B: recompute interp, normalize, write --------
__global__ void normB_kernel(const float* __restrict__ vf,
                             const float* __restrict__ gamma,
                             const float* __restrict__ beta,
                             float* __restrict__ out, int Nv, int C, int lv)
{
    const int c   = threadIdx.x;            // blockDim.x == C
    const int b   = blockIdx.y;
    const int blk = blockIdx.x;
    const int pn  = NP / PB;

    const float* base = vf + (size_t)b * Nv * C;
    float m = g_mu[b * C + c];
    float gr = gamma[c] * g_rstd[b * C + c];
    float bt = beta[c];
    int p0 = blk * pn;
    for (int k = 0; k < pn; k++) {
        int p = p0 + k;
        size_t o = ((size_t)lv * BATCH * NP + (size_t)b * NP + p) * 3;
        int   i0 = g_idx[o], i1 = g_idx[o + 1], i2 = g_idx[o + 2];
        float w0 = g_w[o],   w1 = g_w[o + 1],   w2 = g_w[o + 2];
        float v = fmaf(w2, __ldg(&base[(size_t)i2 * C + c]),
                  fmaf(w1, __ldg(&base[(size_t)i1 * C + c]),
                       w0 * __ldg(&base[(size_t)i0 * C + c])));
        out[((size_t)b * NP + p) * C + c] = fmaf(gr, v - m, bt);
    }
}

// ---------------- launch ------------------------------------------------------
static inline int gs_for(int nv) {
    if (nv >= 32768) return 32;
    if (nv >= 4096)  return 16;
    return 8;
}

extern "C" void kernel_launch(void* const* d_in, const int* in_sizes, int n_in,
                              void* d_out, int out_size)
{
    const float* pt  = (const float*)d_in[0];
    float*       out = (float*)d_out;

    int nv[NLEV], cs[NLEV];
    for (int L = 0; L < NLEV; L++) {
        nv[L] = in_sizes[1 + 4 * L] / (BATCH * 3);
        cs[L] = in_sizes[2 + 4 * L] / (BATCH * nv[L]);
    }

    GridParams gp;
    int cbase = 0, svb = 0, maxnv = 0;
    for (int L = 0; L < NLEV; L++) {
        for (int b = 0; b < BATCH; b++) {
            int s = L * 2 + b;
            gp.vc[s] = (const float*)d_in[1 + 4 * L] + (size_t)b * nv[L] * 3;
            gp.nv[s] = nv[L];
            gp.gs[s] = gs_for(nv[L]);
            gp.cellbase[s] = cbase;
            gp.offbase[s]  = cbase + s;        // +1 sentinel per earlier slot
            gp.svbase[s]   = svb;
            cbase += gp.gs[s] * gp.gs[s] * gp.gs[s];
            svb   += nv[L];
            if (nv[L] > maxnv) maxnv = nv[L];
        }
    }
    int totcells = cbase;
    int nvblocks = (maxnv + 255) / 256;

    init_kernel<<<(totcells + 255) / 256, 256>>>(totcells);
    bbox_kernel<<<dim3(nvblocks, NSLOT), 256>>>(gp);
    count_kernel<<<dim3(nvblocks, NSLOT), 256>>>(gp);
    scan_kernel<<<NSLOT, 1024>>>(gp);
    scatter_kernel<<<dim3(nvblocks, NSLOT), 256>>>(gp);
    query_kernel<<<NLEV * BATCH * NP / 256, 256>>>(pt, gp);

    size_t off = 0;
    for (int L = 0; L < NLEV; L++) {
        const float* vf    = (const float*)d_in[2 + 4 * L];
        const float* gamma = (const float*)d_in[3 + 4 * L];
        const float* beta  = (const float*)d_in[4 + 4 * L];
        const int C = cs[L];
        float* o = out + off;

        statsA_kernel<<<dim3(PB, BATCH), C>>>(vf, nv[L], C, L);
        stats_final_kernel<<<1, 512>>>(C);
        normB_kernel<<<dim3(PB, BATCH), C>>>(vf, gamma, beta, o, nv[L], C, L);

        off += (size_t)BATCH * NP * C;
    }
    (void)n_in; (void)out_size;
}

// round 5
// speedup vs baseline: 5.2020x; 1.4273x over previous
#include <cuda_runtime.h>
#include <math.h>
#include <float.h>

#define BATCH 2
#define NP    32768
#define NLEV  4
#define NSLOT 8            // (level, batch) slots
#define PB    256          // stats partial chunks per batch
#define MAXC  256
#define CHUNK 512          // cells per scan chunk
#define MAXCHUNK 192

// ---------------- static device scratch (no allocations allowed) ------------
__device__ unsigned g_bb  [NSLOT * 6];      // encoded bbox: min x,y,z / max x,y,z
__device__ int      g_cnt [90000];
__device__ int      g_off [90000];          // +1 sentinel per slot
__device__ int      g_fill[90000];
__device__ int      g_bsum[MAXCHUNK];
__device__ int      g_boff[MAXCHUNK];
__device__ float4   g_svox[131072];         // binned voxels {x,y,z,idx-bits}
__device__ int      g_idx [NLEV * BATCH * NP * 3];
__device__ float    g_w   [NLEV * BATCH * NP * 3];
__device__ float    g_psum[NLEV * BATCH * PB * MAXC];
__device__ float    g_psqs[NLEV * BATCH * PB * MAXC];
__device__ float    g_mu  [NLEV * BATCH * MAXC];
__device__ float    g_rstd[NLEV * BATCH * MAXC];

struct GridParams {
    const float* vc[NSLOT];
    int nv[NSLOT];
    int gs[NSLOT];
    int cellbase[NSLOT];
    int offbase[NSLOT];
    int svbase[NSLOT];
};
struct ScanParams { int cstart[NSLOT + 1]; };   // chunk-index boundaries per slot
struct EpiParams {
    const float* vf[NLEV];
    const float* gamma[NLEV];
    const float* beta[NLEV];
    float* outp[NLEV];
    int C[NLEV];
    int Nv[NLEV];
};

// order-preserving float <-> uint for atomicMin/Max
__device__ __forceinline__ unsigned fenc(float f) {
    unsigned u = __float_as_uint(f);
    return (u & 0x80000000u) ? ~u : (u | 0x80000000u);
}
__device__ __forceinline__ float fdec(unsigned u) {
    unsigned v = (u & 0x80000000u) ? (u & 0x7FFFFFFFu) : ~u;
    return __uint_as_float(v);
}
__device__ __forceinline__ int clampi(int v, int lo, int hi) {
    return v < lo ? lo : (v > hi ? hi : v);
}
__device__ __forceinline__ int chunk_slot(int ch, const ScanParams& sp) {
    int s = 0;
    #pragma unroll
    for (int i = 1; i < NSLOT; i++) if (ch >= sp.cstart[i]) s = i;
    return s;
}

// ---------------- init ------------------------------------------------------
__global__ void init_kernel(int totcells) {
    int i = blockIdx.x * blockDim.x + threadIdx.x;
    if (i < totcells) { g_cnt[i] = 0; g_fill[i] = 0; }
    if (i < NSLOT * 6) g_bb[i] = (i % 6 < 3) ? 0xFFFFFFFFu : 0u;
}

// ---------------- per-slot bbox ---------------------------------------------
__global__ void bbox_kernel(GridParams gp) {
    int s = blockIdx.y;
    int nv = gp.nv[s];
    int i = blockIdx.x * 256 + threadIdx.x;
    float x = FLT_MAX, y = FLT_MAX, z = FLT_MAX;
    float X = -FLT_MAX, Y = -FLT_MAX, Z = -FLT_MAX;
    if (i < nv) {
        const float* v = gp.vc[s] + (size_t)i * 3;
        x = X = v[0]; y = Y = v[1]; z = Z = v[2];
    }
    #pragma unroll
    for (int d = 16; d; d >>= 1) {
        x = fminf(x, __shfl_xor_sync(0xFFFFFFFFu, x, d));
        y = fminf(y, __shfl_xor_sync(0xFFFFFFFFu, y, d));
        z = fminf(z, __shfl_xor_sync(0xFFFFFFFFu, z, d));
        X = fmaxf(X, __shfl_xor_sync(0xFFFFFFFFu, X, d));
        Y = fmaxf(Y, __shfl_xor_sync(0xFFFFFFFFu, Y, d));
        Z = fmaxf(Z, __shfl_xor_sync(0xFFFFFFFFu, Z, d));
    }
    if ((threadIdx.x & 31) == 0) {
        atomicMin(&g_bb[s * 6 + 0], fenc(x));
        atomicMin(&g_bb[s * 6 + 1], fenc(y));
        atomicMin(&g_bb[s * 6 + 2], fenc(z));
        atomicMax(&g_bb[s * 6 + 3], fenc(X));
        atomicMax(&g_bb[s * 6 + 4], fenc(Y));
        atomicMax(&g_bb[s * 6 + 5], fenc(Z));
    }
}

// identical cell computation used by count / scatter / query
__device__ __forceinline__ void load_grid(int s, int gs,
    float& bx0, float& by0, float& bz0, float& sx, float& sy, float& sz) {
    bx0 = fdec(g_bb[s * 6 + 0]); by0 = fdec(g_bb[s * 6 + 1]); bz0 = fdec(g_bb[s * 6 + 2]);
    float bx1 = fdec(g_bb[s * 6 + 3]), by1 = fdec(g_bb[s * 6 + 4]), bz1 = fdec(g_bb[s * 6 + 5]);
    sx = gs / fmaxf(bx1 - bx0, 1e-9f);
    sy = gs / fmaxf(by1 - by0, 1e-9f);
    sz = gs / fmaxf(bz1 - bz0, 1e-9f);
}

// ---------------- count -----------------------------------------------------
__global__ void count_kernel(GridParams gp) {
    int s = blockIdx.y;
    int nv = gp.nv[s];
    int i = blockIdx.x * 256 + threadIdx.x;
    if (i >= nv) return;
    int gs = gp.gs[s];
    float bx0, by0, bz0, sx, sy, sz;
    load_grid(s, gs, bx0, by0, bz0, sx, sy, sz);
    const float* v = gp.vc[s] + (size_t)i * 3;
    int cx = clampi((int)((v[0] - bx0) * sx), 0, gs - 1);
    int cy = clampi((int)((v[1] - by0) * sy), 0, gs - 1);
    int cz = clampi((int)((v[2] - bz0) * sz), 0, gs - 1);
    atomicAdd(&g_cnt[gp.cellbase[s] + (cz * gs + cy) * gs + cx], 1);
}

// ---------------- 3-phase scan ------------------------------------------------
// phase 1: per-chunk local exclusive scan (one 512-thread block per 512 cells)
__global__ __launch_bounds__(CHUNK) void scan1_kernel(GridParams gp, ScanParams sp) {
    __shared__ int ws[16];
    const int ch = blockIdx.x, t = threadIdx.x;
    const int s = chunk_slot(ch, sp);
    const int local = (ch - sp.cstart[s]) * CHUNK + t;
    const int lane = t & 31, wid = t >> 5;

    int v = g_cnt[gp.cellbase[s] + local];
    int sv = v;
    #pragma unroll
    for (int d = 1; d < 32; d <<= 1) {
        int o = __shfl_up_sync(0xFFFFFFFFu, sv, d);
        if (lane >= d) sv += o;
    }
    if (lane == 31) ws[wid] = sv;
    __syncthreads();
    if (wid == 0) {
        int w = (lane < 16) ? ws[lane] : 0;
        #pragma unroll
        for (int d = 1; d < 16; d <<= 1) {
            int o = __shfl_up_sync(0xFFFFFFFFu, w, d);
            if (lane >= d) w += o;
        }
        if (lane < 16) ws[lane] = w;
    }
    __syncthreads();
    int excl = sv - v + (wid ? ws[wid - 1] : 0);
    g_off[gp.offbase[s] + local] = excl;
    if (t == CHUNK - 1) g_bsum[ch] = excl + v;
}

// phase 2: warp w scans slot w's chunk sums; writes sentinel totals
__global__ void scan2_kernel(GridParams gp, ScanParams sp) {
    const int w = threadIdx.x >> 5;       // slot
    const int lane = threadIdx.x & 31;
    const int c0 = sp.cstart[w], c1 = sp.cstart[w + 1];
    int running = 0;
    for (int base = c0; base < c1; base += 32) {
        int i = base + lane;
        int v = (i < c1) ? g_bsum[i] : 0;
        int sv = v;
        #pragma unroll
        for (int d = 1; d < 32; d <<= 1) {
            int o = __shfl_up_sync(0xFFFFFFFFu, sv, d);
            if (lane >= d) sv += o;
        }
        if (i < c1) g_boff[i] = running + sv - v;
        running += __shfl_sync(0xFFFFFFFFu, sv, 31);
    }
    if (lane == 0) {
        int gs = gp.gs[w];
        g_off[gp.offbase[w] + gs * gs * gs] = running;
    }
}

// phase 3: add chunk offsets
__global__ __launch_bounds__(CHUNK) void scan3_kernel(GridParams gp, ScanParams sp) {
    const int ch = blockIdx.x, t = threadIdx.x;
    const int s = chunk_slot(ch, sp);
    const int local = (ch - sp.cstart[s]) * CHUNK + t;
    g_off[gp.offbase[s] + local] += g_boff[ch];
}

// ---------------- scatter ----------------------------------------------------
__global__ void scatter_kernel(GridParams gp) {
    int s = blockIdx.y;
    int nv = gp.nv[s];
    int i = blockIdx.x * 256 + threadIdx.x;
    if (i >= nv) return;
    int gs = gp.gs[s];
    float bx0, by0, bz0, sx, sy, sz;
    load_grid(s, gs, bx0, by0, bz0, sx, sy, sz);
    const float* v = gp.vc[s] + (size_t)i * 3;
    float x = v[0], y = v[1], z = v[2];
    int cx = clampi((int)((x - bx0) * sx), 0, gs - 1);
    int cy = clampi((int)((y - by0) * sy), 0, gs - 1);
    int cz = clampi((int)((z - bz0) * sz), 0, gs - 1);
    int cell = (cz * gs + cy) * gs + cx;
    int pos = g_off[gp.offbase[s] + cell] + atomicAdd(&g_fill[gp.cellbase[s] + cell], 1);
    g_svox[gp.svbase[s] + pos] = make_float4(x, y, z, __int_as_float(i));
}

// ---------------- query: exact 3-NN via expanding shells ---------------------
__device__ __forceinline__ void scan_cell(int cell, int ob, int sb,
    float qx, float qy, float qz,
    float& b0, float& b1, float& b2, int& i0, int& i1, int& i2)
{
    int st = __ldg(&g_off[ob + cell]), en = __ldg(&g_off[ob + cell + 1]);
    for (int j = st; j < en; j++) {
        float4 v = __ldg(&g_svox[sb + j]);
        float dx = qx - v.x, dy = qy - v.y, dz = qz - v.z;
        float d2 = fmaf(dx, dx, fmaf(dy, dy, dz * dz));
        if (d2 < b2) {
            int idx = __float_as_int(v.w);
            if (d2 < b1) {
                b2 = b1; i2 = i1;
                if (d2 < b0) { b1 = b0; i1 = i0; b0 = d2; i0 = idx; }
                else         { b1 = d2; i1 = idx; }
            } else { b2 = d2; i2 = idx; }
        }
    }
}

__global__ __launch_bounds__(256) void query_kernel(
    const float* __restrict__ pt, GridParams gp)
{
    int gid = blockIdx.x * 256 + threadIdx.x;   // over NLEV*BATCH*NP
    int p  = gid & (NP - 1);
    int bl = gid >> 15;                         // 0..7
    int b  = bl & 1;
    int L  = bl >> 1;
    int s  = L * 2 + b;

    const float* q3 = pt + ((size_t)b * NP + p) * 3;
    float qx = q3[0], qy = q3[1], qz = q3[2];

    int gs = gp.gs[s];
    float bx0, by0, bz0, sx, sy, sz;
    load_grid(s, gs, bx0, by0, bz0, sx, sy, sz);
    float csx = 1.0f / sx, csy = 1.0f / sy, csz = 1.0f / sz;

    int cx = clampi((int)((qx - bx0) * sx), 0, gs - 1);
    int cy = clampi((int)((qy - by0) * sy), 0, gs - 1);
    int cz = clampi((int)((qz - bz0) * sz), 0, gs - 1);

    const int ob = gp.offbase[s];
    const int sb = gp.svbase[s];

    float b0 = FLT_MAX, b1 = FLT_MAX, b2 = FLT_MAX;
    int i0 = 0, i1 = 0, i2 = 0;

    for (int R = 0; R <= 2 * gs; R++) {
        int zlo = max(cz - R, 0), zhi = min(cz + R, gs - 1);
        for (int z = zlo; z <= zhi; z++) {
            bool zedge = (z == cz - R) || (z == cz + R);
            int ylo = max(cy - R, 0), yhi = min(cy + R, gs - 1);
            for (int y = ylo; y <= yhi; y++) {
                bool yedge = (y == cy - R) || (y == cy + R);
                int rowbase = (z * gs + y) * gs;
                if (zedge || yedge) {
                    int xlo = max(cx - R, 0), xhi = min(cx + R, gs - 1);
                    for (int x = xlo; x <= xhi; x++)
                        scan_cell(rowbase + x, ob, sb, qx, qy, qz, b0, b1, b2, i0, i1, i2);
                } else {
                    int xm = cx - R;
                    if (xm >= 0) scan_cell(rowbase + xm, ob, sb, qx, qy, qz, b0, b1, b2, i0, i1, i2);
                    int xp = cx + R;
                    if (xp < gs) scan_cell(rowbase + xp, ob, sb, qx, qy, qz, b0, b1, b2, i0, i1, i2);
                }
            }
        }
        // clearance of scanned box (per-dim; grid-edge faces are fully covered)
        float cl = FLT_MAX;
        if (cx - R > 0)      cl = fminf(cl, qx - (bx0 + (cx - R) * csx));
        if (cx + R < gs - 1) cl = fminf(cl, (bx0 + (cx + R + 1) * csx) - qx);
        if (cy - R > 0)      cl = fminf(cl, qy - (by0 + (cy - R) * csy));
        if (cy + R < gs - 1) cl = fminf(cl, (by0 + (cy + R + 1) * csy) - qy);
        if (cz - R > 0)      cl = fminf(cl, qz - (bz0 + (cz - R) * csz));
        if (cz + R < gs - 1) cl = fminf(cl, (bz0 + (cz + R + 1) * csz) - qz);
        if (cl == FLT_MAX) break;                 // whole grid scanned
        cl -= 1e-3f;                              // fp safety slack
        if (cl > 0.0f && b2 <= cl * cl) break;
    }

    float w0 = 1.0f / (sqrtf(b0) + 1e-8f);
    float w1 = 1.0f / (sqrtf(b1) + 1e-8f);
    float w2 = 1.0f / (sqrtf(b2) + 1e-8f);
    float inv = 1.0f / (w0 + w1 + w2);

    size_t o = ((size_t)L * BATCH * NP + (size_t)b * NP + p) * 3;
    g_idx[o] = i0; g_idx[o + 1] = i1; g_idx[o + 2] = i2;
    g_w[o] = w0 * inv; g_w[o + 1] = w1 * inv; g_w[o + 2] = w2 * inv;
}

// ---------------- fused epilogue A: interp-on-the-fly -> BN partial stats ----
__global__ __launch_bounds__(MAXC) void statsA_all(EpiParams ep)
{
    const int L   = blockIdx.z;
    const int b   = blockIdx.y;
    const int blk = blockIdx.x;             // PB chunks
    const int c   = threadIdx.x;
    const int C   = ep.C[L];
    if (c >= C) return;
    const int pn  = NP / PB;                // 128

    const float* base = ep.vf[L] + (size_t)b * ep.Nv[L] * C;
    float s = 0.f, q = 0.f;
    int p0 = blk * pn;
    for (int k = 0; k < pn; k++) {
        size_t o = ((size_t)L * BATCH * NP + (size_t)b * NP + (p0 + k)) * 3;
        int   i0 = g_idx[o], i1 = g_idx[o + 1], i2 = g_idx[o + 2];
        float w0 = g_w[o],   w1 = g_w[o + 1],   w2 = g_w[o + 2];
        float v = fmaf(w2, __ldg(&base[(size_t)i2 * C + c]),
                  fmaf(w1, __ldg(&base[(size_t)i1 * C + c]),
                       w0 * __ldg(&base[(size_t)i0 * C + c])));
        s += v;
        q = fmaf(v, v, q);
    }
    size_t po = (((size_t)L * BATCH + b) * PB + blk) * MAXC + c;
    g_psum[po] = s;
    g_psqs[po] = q;
}

// ---------------- fused epilogue F: parallel finalize -------------------------
__global__ void statsF_all(EpiParams ep)
{
    __shared__ float ss[8][32], sq[8][32];
    const int L = blockIdx.z, b = blockIdx.y;
    const int tx = threadIdx.x, ty = threadIdx.y;
    const int c = blockIdx.x * 32 + tx;
    const int C = ep.C[L];

    float s = 0.f, q = 0.f;
    if (c < C) {
        size_t base = ((size_t)L * BATCH + b) * PB * MAXC + c;
        for (int k = ty; k < PB; k += 8) {
            s += g_psum[base + (size_t)k * MAXC];
            q += g_psqs[base + (size_t)k * MAXC];
        }
    }
    ss[ty][tx] = s; sq[ty][tx] = q;
    __syncthreads();
    if (ty == 0 && c < C) {
        #pragma unroll
        for (int r = 1; r < 8; r++) { s += ss[r][tx]; q += sq[r][tx]; }
        float m   = s * (1.0f / NP);
        float var = q * (1.0f / NP) - m * m;      // biased var, matches jnp.var
        size_t mo = ((size_t)L * BATCH + b) * MAXC + c;
        g_mu[mo]   = m;
        g_rstd[mo] = rsqrtf(var + 1e-5f);
    }
}

// ---------------- fused epilogue B: recompute interp, normalize, write --------
__global__ __launch_bounds__(MAXC) void normB_all(EpiParams ep)
{
    const int L   = blockIdx.z;
    const int b   = blockIdx.y;
    const int blk = blockIdx.x;
    const int c   = threadIdx.x;
    const int C   = ep.C[L];
    if (c >= C) return;
    const int pn  = NP / PB;

    const float* base = ep.vf[L] + (size_t)b * ep.Nv[L] * C;
    size_t mo = ((size_t)L * BATCH + b) * MAXC + c;
    float m  = g_mu[mo];
    float gr = ep.gamma[L][c] * g_rstd[mo];
    float bt = ep.beta[L][c];
    float* outp = ep.outp[L];
    int p0 = blk * pn;
    for (int k = 0; k < pn; k++) {
        int p = p0 + k;
        size_t o = ((size_t)L * BATCH * NP + (size_t)b * NP + p) * 3;
        int   i0 = g_idx[o], i1 = g_idx[o + 1], i2 = g_idx[o + 2];
        float w0 = g_w[o],   w1 = g_w[o + 1],   w2 = g_w[o + 2];
        float v = fmaf(w2, __ldg(&base[(size_t)i2 * C + c]),
                  fmaf(w1, __ldg(&base[(size_t)i1 * C + c]),
                       w0 * __ldg(&base[(size_t)i0 * C + c])));
        outp[((size_t)b * NP + p) * C + c] = fmaf(gr, v - m, bt);
    }
}

// ---------------- launch ------------------------------------------------------
static inline int gs_for(int nv) {
    if (nv >= 32768) return 32;
    if (nv >= 4096)  return 16;
    return 8;
}

extern "C" void kernel_launch(void* const* d_in, const int* in_sizes, int n_in,
                              void* d_out, int out_size)
{
    const float* pt  = (const float*)d_in[0];
    float*       out = (float*)d_out;

    int nv[NLEV], cs[NLEV];
    for (int L = 0; L < NLEV; L++) {
        nv[L] = in_sizes[1 + 4 * L] / (BATCH * 3);
        cs[L] = in_sizes[2 + 4 * L] / (BATCH * nv[L]);
    }

    GridParams gp;
    ScanParams sp;
    int cbase = 0, svb = 0, maxnv = 0, nchunks = 0;
    for (int L = 0; L < NLEV; L++) {
        for (int b = 0; b < BATCH; b++) {
            int s = L * 2 + b;
            gp.vc[s] = (const float*)d_in[1 + 4 * L] + (size_t)b * nv[L] * 3;
            gp.nv[s] = nv[L];
            gp.gs[s] = gs_for(nv[L]);
            gp.cellbase[s] = cbase;
            gp.offbase[s]  = cbase + s;        // +1 sentinel per earlier slot
            gp.svbase[s]   = svb;
            sp.cstart[s]   = nchunks;
            int ncell = gp.gs[s] * gp.gs[s] * gp.gs[s];
            cbase   += ncell;
            svb     += nv[L];
            nchunks += ncell / CHUNK;
            if (nv[L] > maxnv) maxnv = nv[L];
        }
    }
    sp.cstart[NSLOT] = nchunks;
    int totcells = cbase;
    int nvblocks = (maxnv + 255) / 256;

    EpiParams ep;
    size_t off = 0;
    for (int L = 0; L < NLEV; L++) {
        ep.vf[L]    = (const float*)d_in[2 + 4 * L];
        ep.gamma[L] = (const float*)d_in[3 + 4 * L];
        ep.beta[L]  = (const float*)d_in[4 + 4 * L];
        ep.outp[L]  = out + off;
        ep.C[L]     = cs[L];
        ep.Nv[L]    = nv[L];
        off += (size_t)BATCH * NP * cs[L];
    }

    init_kernel<<<(totcells + 255) / 256, 256>>>(totcells);
    bbox_kernel<<<dim3(nvblocks, NSLOT), 256>>>(gp);
    count_kernel<<<dim3(nvblocks, NSLOT), 256>>>(gp);
    scan1_kernel<<<nchunks, CHUNK>>>(gp, sp);
    scan2_kernel<<<1, NSLOT * 32>>>(gp, sp);
    scan3_kernel<<<nchunks, CHUNK>>>(gp, sp);
    scatter_kernel<<<dim3(nvblocks, NSLOT), 256>>>(gp);
    query_kernel<<<NLEV * BATCH * NP / 256, 256>>>(pt, gp);

    statsA_all<<<dim3(PB, BATCH, NLEV), MAXC>>>(ep);
    statsF_all<<<dim3(MAXC / 32, BATCH, NLEV), dim3(32, 8)>>>(ep);
    normB_all<<<dim3(PB, BATCH, NLEV), MAXC>>>(ep);

    (void)n_in; (void)out_size;
}